// round 13
// baseline (speedup 1.0000x reference)
#include <cuda_runtime.h>
#include <cuda_fp16.h>

#define NN 20000
#define EE 320000
#define TT 16
#define FIN 9
#define HID 128
#define HEADS 8
#define D1 1024          // HEADS*HID
#define MM (TT * NN)     // 320000 flat rows
#define PBLK 160
#define PCH 125
#define FULL 0xffffffffu

// ---------------- static device scratch ----------------
__device__ int   g_is64;
__device__ int   g_cnt[NN];
__device__ int   g_rowptr[NN + 1];
__device__ int   g_cursor[NN];
__device__ int   g_col[EE];
__device__ float g_w1as[FIN * HEADS];
__device__ float g_w1ad[FIN * HEADS];
__device__ float g_als1[(size_t)TT * NN * HEADS];
__device__ float g_ald1[(size_t)TT * NN * HEADS];
__device__ float g_xagg[(size_t)TT * NN * 72];
__device__ __align__(16) __half g_out1[(size_t)MM * D1];   // 655 MB fp16
__device__ __align__(16) __half g_W2h[D1 * HID];
__device__ __align__(16) __half g_h2[(size_t)MM * HID];
__device__ float g_als2[(size_t)TT * NN];
__device__ float g_ald2[(size_t)TT * NN];
__device__ __align__(16) __half g_out2h[(size_t)TT * NN * HID];
__device__ float g_partial[(size_t)TT * PBLK * HID];
__device__ float g_emb[TT * HID];

// ---------------- CSR setup ----------------
__global__ void k_zc() {
    int i = blockIdx.x * blockDim.x + threadIdx.x;
    if (i < NN) g_cnt[i] = 0;
}

__global__ void k_count(const void* __restrict__ ei) {
    int e = blockIdx.x * blockDim.x + threadIdx.x;
    if (e >= EE) return;
    const long long* p64 = (const long long*)ei;
    int ok = 1;
#pragma unroll
    for (int q = 0; q < 8; q++) {
        long long v = p64[q];
        if (v < 0 || v >= NN) ok = 0;
    }
    if (e == 0) g_is64 = ok;
    int d = ok ? (int)p64[(size_t)EE + e] : ((const int*)ei)[(size_t)EE + e];
    if (d >= 0 && d < NN) atomicAdd(&g_cnt[d], 1);
}

__global__ void k_scan() {
    __shared__ int part[1024];
    int tid = threadIdx.x;
    const int CH = (NN + 1023) / 1024;
    int base = tid * CH;
    int s = 0;
    for (int i = 0; i < CH; i++) {
        int idx = base + i;
        if (idx < NN) s += g_cnt[idx];
    }
    part[tid] = s;
    __syncthreads();
    for (int off = 1; off < 1024; off <<= 1) {
        int v = (tid >= off) ? part[tid - off] : 0;
        __syncthreads();
        part[tid] += v;
        __syncthreads();
    }
    int run = part[tid] - s;
    for (int i = 0; i < CH; i++) {
        int idx = base + i;
        if (idx < NN) {
            g_rowptr[idx] = run;
            g_cursor[idx] = run;
            run += g_cnt[idx];
        }
    }
    if (tid == 1023) g_rowptr[NN] = part[1023];
}

__global__ void k_fill(const void* __restrict__ ei) {
    int e = blockIdx.x * blockDim.x + threadIdx.x;
    if (e < EE) {
        int is64 = g_is64;
        int s = is64 ? (int)((const long long*)ei)[e] : ((const int*)ei)[e];
        int d = is64 ? (int)((const long long*)ei)[(size_t)EE + e]
                     : ((const int*)ei)[(size_t)EE + e];
        if (s >= 0 && s < NN && d >= 0 && d < NN) {
            int p = atomicAdd(&g_cursor[d], 1);
            g_col[p] = s;
        }
    }
}

// ---------------- prep: W2 -> fp16, W1a projections ----------------
__global__ void k_prep(const float* __restrict__ W2, const float* __restrict__ W1,
                       const float* __restrict__ as1, const float* __restrict__ ad1) {
    int i = blockIdx.x * blockDim.x + threadIdx.x;
    if (i < D1 * HID) g_W2h[i] = __float2half(W2[i]);
    if (blockIdx.x == 0 && threadIdx.x < FIN * HEADS) {
        int r = threadIdx.x / HEADS, h = threadIdx.x % HEADS;
        float s1 = 0.f, s2 = 0.f;
        for (int c = 0; c < HID; c++) {
            float wv = W1[r * D1 + h * HID + c];
            s1 += wv * as1[h * HID + c];
            s2 += wv * ad1[h * HID + c];
        }
        g_w1as[threadIdx.x] = s1;
        g_w1ad[threadIdx.x] = s2;
    }
}

// ---------------- GAT1 attention logits for all (t,n) ----------------
__global__ void __launch_bounds__(256) k_logits1(const float* __restrict__ x) {
    int id = blockIdx.x * blockDim.x + threadIdx.x;
    if (id >= TT * NN) return;
    float xv[FIN];
#pragma unroll
    for (int r = 0; r < FIN; r++) xv[r] = x[(size_t)id * FIN + r];
#pragma unroll
    for (int h = 0; h < HEADS; h++) {
        float s1 = 0.f, s2 = 0.f;
#pragma unroll
        for (int r = 0; r < FIN; r++) {
            s1 += xv[r] * g_w1as[r * HEADS + h];
            s2 += xv[r] * g_w1ad[r * HEADS + h];
        }
        g_als1[(size_t)id * HEADS + h] = s1;
        g_ald1[(size_t)id * HEADS + h] = s2;
    }
}

// ---------------- GAT1 aggregation, raw feature space (warp-per-node) ----------------
__global__ void __launch_bounds__(256) k_agg1x(const float* __restrict__ x) {
    int w = threadIdx.x >> 5, lane = threadIdx.x & 31;
    int n = blockIdx.x * 8 + w;
    int t = blockIdx.y;
    if (n >= NN) return;
    const float* als = g_als1 + (size_t)t * NN * HEADS;
    const float* ald = g_ald1 + (size_t)t * NN * HEADS;
    const float* xt  = x + (size_t)t * NN * FIN;
    int start = g_rowptr[n];
    int deg = g_rowptr[n + 1] - start + 1;

    int h8 = lane & 7;
    float aldh = ald[n * HEADS + h8];

    float sum = 0.f;
    for (int i = lane >> 3; i < deg; i += 4) {
        int s = (i < deg - 1) ? g_col[start + i] : n;
        float l = als[s * HEADS + h8] + aldh;
        l = (l > 0.f) ? l : 0.2f * l;
        sum += __expf(l);
    }
    sum += __shfl_xor_sync(FULL, sum, 8);
    sum += __shfl_xor_sync(FULL, sum, 16);
    float inv = 1.f / (sum + 1e-16f);

    int h = lane >> 2, q = lane & 3;
    float invh = __shfl_sync(FULL, inv, h);
    float a0 = 0.f, a1 = 0.f, a2 = 0.f;
    const int* colp = &g_col[start];
    for (int i = 0; i < deg; i++) {
        int s = (i < deg - 1) ? colp[i] : n;
        float l = als[s * HEADS + h8] + aldh;
        l = (l > 0.f) ? l : 0.2f * l;
        float e = __expf(l);
        float alpha = __shfl_sync(FULL, e, h) * invh;
        const float* xs = &xt[(size_t)s * FIN];
        a0 += alpha * xs[q];
        a1 += alpha * xs[q + 4];
        if (q == 0) a2 += alpha * xs[8];
    }
    float* dst = &g_xagg[((size_t)t * NN + n) * 72 + h * FIN];
    dst[q] = a0;
    dst[q + 4] = a1;
    if (q == 0) dst[8] = a2;
}

// ---------------- expand: out1 = relu(xagg @ W1 + b1)  (fp16, W1 in registers) ----------------
__global__ void __launch_bounds__(256) k_expand(const float* __restrict__ W1,
                                                const float* __restrict__ b1) {
    __shared__ float sxa[32 * 72];
    int tid = threadIdx.x;
    int gcol = tid * 4;
    int head = tid >> 5;
    int row0 = blockIdx.x * 32;

    float w[FIN][4];
#pragma unroll
    for (int r = 0; r < FIN; r++) {
        float4 wv = *(const float4*)&W1[r * D1 + gcol];
        w[r][0] = wv.x; w[r][1] = wv.y; w[r][2] = wv.z; w[r][3] = wv.w;
    }
    float4 bias = *(const float4*)&b1[gcol];

    for (int i = tid; i < 32 * 72; i += 256)
        sxa[i] = g_xagg[(size_t)row0 * 72 + i];
    __syncthreads();

    for (int rr = 0; rr < 32; rr++) {
        const float* xa = &sxa[rr * 72 + head * FIN];
        float v0 = bias.x, v1 = bias.y, v2 = bias.z, v3 = bias.w;
#pragma unroll
        for (int r = 0; r < FIN; r++) {
            float xr = xa[r];
            v0 += xr * w[r][0];
            v1 += xr * w[r][1];
            v2 += xr * w[r][2];
            v3 += xr * w[r][3];
        }
        __half2 p0 = __floats2half2_rn(fmaxf(v0, 0.f), fmaxf(v1, 0.f));
        __half2 p1 = __floats2half2_rn(fmaxf(v2, 0.f), fmaxf(v3, 0.f));
        uint2 o;
        o.x = *(unsigned*)&p0; o.y = *(unsigned*)&p1;
        *(uint2*)&g_out1[(size_t)(row0 + rr) * D1 + gcol] = o;
    }
}

// ---------------- pipelined TC GEMM: h2[MM,128] = out1[MM,1024] @ W2h ----------------
__device__ __forceinline__ int aswz32(int row, int col) {
    int chunk = (col >> 3) & 3;
    int sw = chunk ^ ((row >> 1) & 3);
    return row * 32 + sw * 8 + (col & 7);
}
__device__ __forceinline__ int bswz(int row, int col) {
    int chunk = col >> 3;
    int sw = (chunk & 8) | ((chunk ^ row) & 7);
    return row * 128 + sw * 8 + (col & 7);
}

__global__ void __launch_bounds__(256) k_gemm() {
    __shared__ __half As[2][128 * 32];
    __shared__ __half Bs[2][32 * 128];
    int tid = threadIdx.x;
    int lane = tid & 31, w = tid >> 5;
    int wm = w & 3, wn = w >> 2;
    size_t m0 = (size_t)blockIdx.x * 128;

    float acc[2][8][4];
#pragma unroll
    for (int mt = 0; mt < 2; mt++)
#pragma unroll
        for (int nt = 0; nt < 8; nt++)
#pragma unroll
            for (int q = 0; q < 4; q++) acc[mt][nt][q] = 0.f;

    int arow = tid >> 1;
    int ac0 = (tid & 1) * 2;
    int brow = tid >> 3;
    int bc0 = (tid & 7) * 2;

    const __half* aSrc0 = &g_out1[(m0 + arow) * D1];

#define ISSUE_STAGE(kt, buf)                                                          \
    do {                                                                              \
        _Pragma("unroll")                                                             \
        for (int c = 0; c < 2; c++) {                                                 \
            int ch = ac0 + c;                                                         \
            unsigned d_ = (unsigned)__cvta_generic_to_shared(                         \
                &As[buf][aswz32(arow, ch * 8)]);                                      \
            const __half* s_ = aSrc0 + (kt) * 32 + ch * 8;                            \
            asm volatile("cp.async.ca.shared.global [%0], [%1], 16;" ::               \
                         "r"(d_), "l"(s_));                                           \
        }                                                                             \
        _Pragma("unroll")                                                             \
        for (int c = 0; c < 2; c++) {                                                 \
            int ch = bc0 + c;                                                         \
            unsigned d_ = (unsigned)__cvta_generic_to_shared(                         \
                &Bs[buf][bswz(brow, ch * 8)]);                                        \
            const __half* s_ = &g_W2h[(size_t)((kt) * 32 + brow) * HID + ch * 8];     \
            asm volatile("cp.async.ca.shared.global [%0], [%1], 16;" ::               \
                         "r"(d_), "l"(s_));                                           \
        }                                                                             \
        asm volatile("cp.async.commit_group;");                                       \
    } while (0)

    ISSUE_STAGE(0, 0);

    for (int kt = 0; kt < 32; kt++) {
        int buf = kt & 1;
        asm volatile("cp.async.wait_group 0;");
        __syncthreads();
        if (kt + 1 < 32) ISSUE_STAGE(kt + 1, buf ^ 1);

#pragma unroll
        for (int kk = 0; kk < 32; kk += 16) {
            unsigned a[2][4];
#pragma unroll
            for (int mt = 0; mt < 2; mt++) {
                int r = wm * 32 + mt * 16 + (lane & 15);
                int cc = kk + (lane >> 4) * 8;
                unsigned addr = (unsigned)__cvta_generic_to_shared(&As[buf][aswz32(r, cc)]);
                asm volatile("ldmatrix.sync.aligned.m8n8.x4.shared.b16 {%0,%1,%2,%3}, [%4];"
                             : "=r"(a[mt][0]), "=r"(a[mt][1]), "=r"(a[mt][2]), "=r"(a[mt][3])
                             : "r"(addr));
            }
            unsigned b[8][2];
#pragma unroll
            for (int nt = 0; nt < 8; nt++) {
                int r = kk + (lane & 15);
                int cc = wn * 64 + nt * 8;
                unsigned addr = (unsigned)__cvta_generic_to_shared(&Bs[buf][bswz(r, cc)]);
                asm volatile("ldmatrix.sync.aligned.m8n8.x2.trans.shared.b16 {%0,%1}, [%2];"
                             : "=r"(b[nt][0]), "=r"(b[nt][1]) : "r"(addr));
            }
#pragma unroll
            for (int mt = 0; mt < 2; mt++)
#pragma unroll
                for (int nt = 0; nt < 8; nt++) {
                    asm volatile(
                        "mma.sync.aligned.m16n8k16.row.col.f32.f16.f16.f32 "
                        "{%0,%1,%2,%3}, {%4,%5,%6,%7}, {%8,%9}, {%0,%1,%2,%3};"
                        : "+f"(acc[mt][nt][0]), "+f"(acc[mt][nt][1]),
                          "+f"(acc[mt][nt][2]), "+f"(acc[mt][nt][3])
                        : "r"(a[mt][0]), "r"(a[mt][1]), "r"(a[mt][2]), "r"(a[mt][3]),
                          "r"(b[nt][0]), "r"(b[nt][1]));
                }
        }
        __syncthreads();
    }
#undef ISSUE_STAGE

#pragma unroll
    for (int mt = 0; mt < 2; mt++) {
        size_t rbase = m0 + wm * 32 + mt * 16 + (lane >> 2);
#pragma unroll
        for (int nt = 0; nt < 8; nt++) {
            int col = wn * 64 + nt * 8 + (lane & 3) * 2;
            *(__half2*)&g_h2[rbase * HID + col] =
                __floats2half2_rn(acc[mt][nt][0], acc[mt][nt][1]);
            *(__half2*)&g_h2[(rbase + 8) * HID + col] =
                __floats2half2_rn(acc[mt][nt][2], acc[mt][nt][3]);
        }
    }
}

// ---------------- GAT2 attention logits (batched) ----------------
__global__ void __launch_bounds__(256) k_al2(const float* __restrict__ as2,
                                             const float* __restrict__ ad2) {
    int w = threadIdx.x >> 5, lane = threadIdx.x & 31;
    int n = blockIdx.x * 8 + w;
    int t = blockIdx.y;
    if (n >= NN) return;
    uint2 v = *(const uint2*)&g_h2[((size_t)t * NN + n) * HID + lane * 4];
    float2 f0 = __half22float2(*(__half2*)&v.x);
    float2 f1 = __half22float2(*(__half2*)&v.y);
    float4 a = *(const float4*)&as2[lane * 4];
    float4 d = *(const float4*)&ad2[lane * 4];
    float ps = f0.x * a.x + f0.y * a.y + f1.x * a.z + f1.y * a.w;
    float pd = f0.x * d.x + f0.y * d.y + f1.x * d.z + f1.y * d.w;
#pragma unroll
    for (int off = 16; off; off >>= 1) {
        ps += __shfl_xor_sync(FULL, ps, off);
        pd += __shfl_xor_sync(FULL, pd, off);
    }
    if (lane == 0) {
        g_als2[(size_t)t * NN + n] = ps;
        g_ald2[(size_t)t * NN + n] = pd;
    }
}

// ---------------- GAT2 softmax + aggregation (batched) ----------------
__global__ void __launch_bounds__(256) k_agg2(const float* __restrict__ b2) {
    int w = threadIdx.x >> 5, lane = threadIdx.x & 31;
    int n = blockIdx.x * 8 + w;
    int t = blockIdx.y;
    if (n >= NN) return;
    const __half* h2 = g_h2 + (size_t)t * NN * HID;
    const float* als = g_als2 + (size_t)t * NN;
    int start = g_rowptr[n];
    int deg = g_rowptr[n + 1] - start + 1;
    float aldn = g_ald2[(size_t)t * NN + n];

    float sum = 0.f;
    for (int i = lane; i < deg; i += 32) {
        int s = (i < deg - 1) ? g_col[start + i] : n;
        float l = als[s] + aldn;
        l = (l > 0.f) ? l : 0.2f * l;
        sum += __expf(l);
    }
#pragma unroll
    for (int off = 16; off; off >>= 1) sum += __shfl_xor_sync(FULL, sum, off);
    float inv = 1.f / (sum + 1e-16f);

    float a0 = 0.f, a1 = 0.f, a2 = 0.f, a3 = 0.f;
    const int* colp = &g_col[start];
    for (int i = 0; i < deg; i++) {
        int s = (i < deg - 1) ? colp[i] : n;
        float l = als[s] + aldn;
        l = (l > 0.f) ? l : 0.2f * l;
        float al = __expf(l) * inv;
        uint2 v = *(const uint2*)&h2[(size_t)s * HID + lane * 4];
        float2 f0 = __half22float2(*(__half2*)&v.x);
        float2 f1 = __half22float2(*(__half2*)&v.y);
        a0 += al * f0.x; a1 += al * f0.y;
        a2 += al * f1.x; a3 += al * f1.y;
    }
    float4 b = *(const float4*)&b2[lane * 4];
    __half2 p0 = __floats2half2_rn(fmaxf(a0 + b.x, 0.f), fmaxf(a1 + b.y, 0.f));
    __half2 p1 = __floats2half2_rn(fmaxf(a2 + b.z, 0.f), fmaxf(a3 + b.w, 0.f));
    uint2 o;
    o.x = *(unsigned*)&p0; o.y = *(unsigned*)&p1;
    *(uint2*)&g_out2h[((size_t)t * NN + n) * HID + lane * 4] = o;
}

// ---------------- deterministic mean pool (batched) ----------------
__global__ void __launch_bounds__(128) k_pool_a() {
    int c = threadIdx.x, b = blockIdx.x, t = blockIdx.y;
    int n0 = b * PCH, n1 = min(n0 + PCH, NN);
    float s = 0.f;
    for (int n = n0; n < n1; n++)
        s += __half2float(g_out2h[((size_t)t * NN + n) * HID + c]);
    g_partial[((size_t)t * PBLK + b) * HID + c] = s;
}

__global__ void __launch_bounds__(128) k_pool_b() {
    int c = threadIdx.x, t = blockIdx.x;
    float s = 0.f;
    for (int b = 0; b < PBLK; b++) s += g_partial[((size_t)t * PBLK + b) * HID + c];
    g_emb[t * HID + c] = s * (1.0f / NN);
}

// ---------------- GRU + output head ----------------
__global__ void __launch_bounds__(128) k_gru(
    const float* __restrict__ wih, const float* __restrict__ whh,
    const float* __restrict__ bih, const float* __restrict__ bhh,
    const float* __restrict__ wout, const float* __restrict__ bout,
    float* __restrict__ out) {
    int tid = threadIdx.x;
    __shared__ float h[HID], xt[HID];
    __shared__ float red[4];
    h[tid] = 0.f;
    __syncthreads();
    for (int t = 0; t < TT; t++) {
        xt[tid] = g_emb[t * HID + tid];
        __syncthreads();
        float gi[3], gh[3];
#pragma unroll
        for (int q = 0; q < 3; q++) {
            int r = q * HID + tid;
            float s1 = bih[r], s2 = bhh[r];
            const float* wi = &wih[(size_t)r * HID];
            const float* wh = &whh[(size_t)r * HID];
            for (int c = 0; c < HID; c++) {
                s1 += xt[c] * wi[c];
                s2 += h[c] * wh[c];
            }
            gi[q] = s1;
            gh[q] = s2;
        }
        float r  = 1.f / (1.f + __expf(-(gi[0] + gh[0])));
        float z  = 1.f / (1.f + __expf(-(gi[1] + gh[1])));
        float nn = tanhf(gi[2] + r * gh[2]);
        float hn = (1.f - z) * nn + z * h[tid];
        __syncthreads();
        h[tid] = hn;
        __syncthreads();
        float v = hn * wout[tid];
        int lane = tid & 31, w = tid >> 5;
        for (int o = 16; o; o >>= 1) v += __shfl_down_sync(FULL, v, o);
        if (lane == 0) red[w] = v;
        __syncthreads();
        if (tid == 0) out[t] = red[0] + red[1] + red[2] + red[3] + bout[0];
        __syncthreads();
    }
}

// ---------------- launch ----------------
// Instrumentation round: duplicate launches with stale (but address-identical)
// inputs to measure hot-kernel costs. All duplicated writes are re-written by
// the real pipeline before consumption (or after their consumers ran), so the
// final output is deterministic and identical.
extern "C" void kernel_launch(void* const* d_in, const int* in_sizes, int n_in,
                              void* d_out, int out_size) {
    const float* x    = (const float*)d_in[0];
    const void*  ei   = d_in[1];
    const float* W1   = (const float*)d_in[2];
    const float* as1  = (const float*)d_in[3];
    const float* ad1  = (const float*)d_in[4];
    const float* b1   = (const float*)d_in[5];
    const float* W2   = (const float*)d_in[6];
    const float* as2  = (const float*)d_in[7];
    const float* ad2  = (const float*)d_in[8];
    const float* b2   = (const float*)d_in[9];
    const float* wih  = (const float*)d_in[10];
    const float* whh  = (const float*)d_in[11];
    const float* bih  = (const float*)d_in[12];
    const float* bhh  = (const float*)d_in[13];
    const float* wout = (const float*)d_in[14];
    const float* bout = (const float*)d_in[15];
    float* out = (float*)d_out;

    k_zc<<<(NN + 255) / 256, 256>>>();                                   // 1
    k_count<<<(EE + 255) / 256, 256>>>(ei);                              // 2
    k_prep<<<(D1 * HID + 255) / 256, 256>>>(W2, W1, as1, ad1);           // 3
    k_gemm<<<MM / 128, 256>>>();                                         // 4 <- ncu capture (dup)
    k_logits1<<<(TT * NN + 255) / 256, 256>>>(x);                        // 5
    k_scan<<<1, 1024>>>();                                               // 6
    k_fill<<<(EE + 255) / 256, 256>>>(ei);                               // 7
    k_agg1x<<<dim3((NN + 7) / 8, TT), 256>>>(x);                         // 8
    k_expand<<<MM / 32, 256>>>(W1, b1);                                  // 9
    k_gemm<<<MM / 128, 256>>>();                                         // 10 (real)
    k_al2<<<dim3((NN + 7) / 8, TT), 256>>>(as2, ad2);                    // 11
    k_agg2<<<dim3((NN + 7) / 8, TT), 256>>>(b2);                         // 12
    k_pool_a<<<dim3(PBLK, TT), 128>>>();                                 // 13
    k_pool_b<<<TT, 128>>>();                                             // 14
    k_agg1x<<<dim3((NN + 7) / 8, TT), 256>>>(x);                         // 15 dup (same output)
    k_expand<<<MM / 32, 256>>>(W1, b1);                                  // 16 dup (same output)
    k_agg2<<<dim3((NN + 7) / 8, TT), 256>>>(b2);                         // 17 dup (g_out2h already consumed)
    k_gru<<<1, 128>>>(wih, whh, bih, bhh, wout, bout, out);              // 18
}

// round 14
// speedup vs baseline: 1.5156x; 1.5156x over previous
#include <cuda_runtime.h>
#include <cuda_fp16.h>

#define NN 20000
#define EE 320000
#define TT 16
#define FIN 9
#define HID 128
#define HEADS 8
#define D1 1024          // HEADS*HID
#define MM (TT * NN)     // 320000 flat rows
#define PBLK 160
#define PCH 125
#define FULL 0xffffffffu

// ---------------- static device scratch ----------------
__device__ int   g_is64;
__device__ int   g_cnt[NN];
__device__ int   g_rowptr[NN + 1];
__device__ int   g_cursor[NN];
__device__ int   g_col[EE];
__device__ float g_w1as[FIN * HEADS];
__device__ float g_w1ad[FIN * HEADS];
__device__ float g_als1[(size_t)TT * NN * HEADS];
__device__ float g_ald1[(size_t)TT * NN * HEADS];
__device__ float g_xagg[(size_t)TT * NN * 72];
__device__ __align__(16) __half g_W1b[HEADS * 10 * HID];   // per-head [10][128]: rows 0-8 = W1, row 9 = b1
__device__ __align__(16) __half g_W2h[D1 * HID];
__device__ __align__(16) __half g_h2[(size_t)MM * HID];
__device__ float g_als2[(size_t)TT * NN];
__device__ float g_ald2[(size_t)TT * NN];
__device__ __align__(16) __half g_out2h[(size_t)TT * NN * HID];
__device__ float g_partial[(size_t)TT * PBLK * HID];
__device__ float g_emb[TT * HID];

// ---------------- CSR setup ----------------
__global__ void k_zc() {
    int i = blockIdx.x * blockDim.x + threadIdx.x;
    if (i < NN) g_cnt[i] = 0;
}

__global__ void k_count(const void* __restrict__ ei) {
    int e = blockIdx.x * blockDim.x + threadIdx.x;
    if (e >= EE) return;
    const long long* p64 = (const long long*)ei;
    int ok = 1;
#pragma unroll
    for (int q = 0; q < 8; q++) {
        long long v = p64[q];
        if (v < 0 || v >= NN) ok = 0;
    }
    if (e == 0) g_is64 = ok;
    int d = ok ? (int)p64[(size_t)EE + e] : ((const int*)ei)[(size_t)EE + e];
    if (d >= 0 && d < NN) atomicAdd(&g_cnt[d], 1);
}

__global__ void k_scan() {
    __shared__ int part[1024];
    int tid = threadIdx.x;
    const int CH = (NN + 1023) / 1024;
    int base = tid * CH;
    int s = 0;
    for (int i = 0; i < CH; i++) {
        int idx = base + i;
        if (idx < NN) s += g_cnt[idx];
    }
    part[tid] = s;
    __syncthreads();
    for (int off = 1; off < 1024; off <<= 1) {
        int v = (tid >= off) ? part[tid - off] : 0;
        __syncthreads();
        part[tid] += v;
        __syncthreads();
    }
    int run = part[tid] - s;
    for (int i = 0; i < CH; i++) {
        int idx = base + i;
        if (idx < NN) {
            g_rowptr[idx] = run;
            g_cursor[idx] = run;
            run += g_cnt[idx];
        }
    }
    if (tid == 1023) g_rowptr[NN] = part[1023];
}

__global__ void k_fill(const void* __restrict__ ei) {
    int e = blockIdx.x * blockDim.x + threadIdx.x;
    if (e < EE) {
        int is64 = g_is64;
        int s = is64 ? (int)((const long long*)ei)[e] : ((const int*)ei)[e];
        int d = is64 ? (int)((const long long*)ei)[(size_t)EE + e]
                     : ((const int*)ei)[(size_t)EE + e];
        if (s >= 0 && s < NN && d >= 0 && d < NN) {
            int p = atomicAdd(&g_cursor[d], 1);
            g_col[p] = s;
        }
    }
}

// ---------------- prep: W2 fp16, W1+b1 per-head fp16, W1a projections ----------------
__global__ void k_prep(const float* __restrict__ W2, const float* __restrict__ W1,
                       const float* __restrict__ as1, const float* __restrict__ ad1,
                       const float* __restrict__ b1) {
    int i = blockIdx.x * blockDim.x + threadIdx.x;
    if (i < D1 * HID) g_W2h[i] = __float2half(W2[i]);
    if (i < HEADS * 10 * HID) {
        int h = i / (10 * HID);
        int rem = i - h * 10 * HID;
        int r = rem >> 7, c = rem & 127;
        g_W1b[i] = __float2half((r < 9) ? W1[r * D1 + h * HID + c] : b1[h * HID + c]);
    }
    if (blockIdx.x == 0 && threadIdx.x < FIN * HEADS) {
        int r = threadIdx.x / HEADS, h = threadIdx.x % HEADS;
        float s1 = 0.f, s2 = 0.f;
        for (int c = 0; c < HID; c++) {
            float wv = W1[r * D1 + h * HID + c];
            s1 += wv * as1[h * HID + c];
            s2 += wv * ad1[h * HID + c];
        }
        g_w1as[threadIdx.x] = s1;
        g_w1ad[threadIdx.x] = s2;
    }
}

// ---------------- GAT1 attention logits for all (t,n) ----------------
__global__ void __launch_bounds__(256) k_logits1(const float* __restrict__ x) {
    int id = blockIdx.x * blockDim.x + threadIdx.x;
    if (id >= TT * NN) return;
    float xv[FIN];
#pragma unroll
    for (int r = 0; r < FIN; r++) xv[r] = x[(size_t)id * FIN + r];
#pragma unroll
    for (int h = 0; h < HEADS; h++) {
        float s1 = 0.f, s2 = 0.f;
#pragma unroll
        for (int r = 0; r < FIN; r++) {
            s1 += xv[r] * g_w1as[r * HEADS + h];
            s2 += xv[r] * g_w1ad[r * HEADS + h];
        }
        g_als1[(size_t)id * HEADS + h] = s1;
        g_ald1[(size_t)id * HEADS + h] = s2;
    }
}

// ---------------- GAT1 aggregation, raw feature space (warp-per-node) ----------------
__global__ void __launch_bounds__(256) k_agg1x(const float* __restrict__ x) {
    int w = threadIdx.x >> 5, lane = threadIdx.x & 31;
    int n = blockIdx.x * 8 + w;
    int t = blockIdx.y;
    if (n >= NN) return;
    const float* als = g_als1 + (size_t)t * NN * HEADS;
    const float* ald = g_ald1 + (size_t)t * NN * HEADS;
    const float* xt  = x + (size_t)t * NN * FIN;
    int start = g_rowptr[n];
    int deg = g_rowptr[n + 1] - start + 1;

    int h8 = lane & 7;
    float aldh = ald[n * HEADS + h8];

    float sum = 0.f;
    for (int i = lane >> 3; i < deg; i += 4) {
        int s = (i < deg - 1) ? g_col[start + i] : n;
        float l = als[s * HEADS + h8] + aldh;
        l = (l > 0.f) ? l : 0.2f * l;
        sum += __expf(l);
    }
    sum += __shfl_xor_sync(FULL, sum, 8);
    sum += __shfl_xor_sync(FULL, sum, 16);
    float inv = 1.f / (sum + 1e-16f);

    int h = lane >> 2, q = lane & 3;
    float invh = __shfl_sync(FULL, inv, h);
    float a0 = 0.f, a1 = 0.f, a2 = 0.f;
    const int* colp = &g_col[start];
    for (int i = 0; i < deg; i++) {
        int s = (i < deg - 1) ? colp[i] : n;
        float l = als[s * HEADS + h8] + aldh;
        l = (l > 0.f) ? l : 0.2f * l;
        float e = __expf(l);
        float alpha = __shfl_sync(FULL, e, h) * invh;
        const float* xs = &xt[(size_t)s * FIN];
        a0 += alpha * xs[q];
        a1 += alpha * xs[q + 4];
        if (q == 0) a2 += alpha * xs[8];
    }
    float* dst = &g_xagg[((size_t)t * NN + n) * 72 + h * FIN];
    dst[q] = a0;
    dst[q + 4] = a1;
    if (q == 0) dst[8] = a2;
}

// ---------------- fused TC GEMM: h2 = relu(xagg@W1+b1) @ W2, A generated in-kernel ----------------
__device__ __forceinline__ int aswz32(int row, int col) {
    int chunk = (col >> 3) & 3;
    int sw = chunk ^ ((row >> 1) & 3);
    return row * 32 + sw * 8 + (col & 7);
}
__device__ __forceinline__ int bswz(int row, int col) {
    int chunk = col >> 3;
    int sw = (chunk & 8) | ((chunk ^ row) & 7);
    return row * 128 + sw * 8 + (col & 7);
}

__global__ void __launch_bounds__(256) k_gemmf() {
    __shared__ __half As[2][128 * 32];       // 16 KB
    __shared__ __half Bs[2][32 * 128];       // 16 KB
    __shared__ __half sW1[2][10 * HID];      // 5 KB (per-head W1+b1, double-buffered)
    int tid = threadIdx.x;
    int lane = tid & 31, w = tid >> 5;
    int wm = w & 3, wn = w >> 2;
    size_t m0 = (size_t)blockIdx.x * 128;

    float acc[2][8][4];
#pragma unroll
    for (int mt = 0; mt < 2; mt++)
#pragma unroll
        for (int nt = 0; nt < 8; nt++)
#pragma unroll
            for (int q = 0; q < 4; q++) acc[mt][nt][q] = 0.f;

    // B-load mapping
    int brow = tid >> 3;
    int bc0 = (tid & 7) * 2;
    // A-generation mapping: thread owns rows {2*rowg, 2*rowg+1}, cols colg*8..+7 of the 32-chunk
    int rowg = tid >> 2;
    int colg = tid & 3;
    const float* xr0p = &g_xagg[(m0 + 2 * rowg) * 72];
    const float* xr1p = xr0p + 72;

#define ISSUE_B(kt, buf)                                                              \
    do {                                                                              \
        _Pragma("unroll")                                                             \
        for (int c = 0; c < 2; c++) {                                                 \
            int ch = bc0 + c;                                                         \
            unsigned d_ = (unsigned)__cvta_generic_to_shared(                         \
                &Bs[buf][bswz(brow, ch * 8)]);                                        \
            const __half* s_ = &g_W2h[(size_t)((kt) * 32 + brow) * HID + ch * 8];     \
            asm volatile("cp.async.ca.shared.global [%0], [%1], 16;" ::               \
                         "r"(d_), "l"(s_));                                           \
        }                                                                             \
    } while (0)

#define STAGE_W1(h, hb)                                                               \
    do {                                                                              \
        if (tid < 160) {                                                              \
            unsigned d_ = (unsigned)__cvta_generic_to_shared(&sW1[hb][tid * 8]);      \
            const __half* s_ = g_W1b + (h) * (10 * HID) + tid * 8;                    \
            asm volatile("cp.async.ca.shared.global [%0], [%1], 16;" ::               \
                         "r"(d_), "l"(s_));                                           \
        }                                                                             \
    } while (0)

    __half2 xh0[FIN], xh1[FIN];
#define LOAD_XAGG(h)                                                                  \
    do {                                                                              \
        _Pragma("unroll")                                                             \
        for (int r = 0; r < FIN; r++) {                                               \
            xh0[r] = __float2half2_rn(xr0p[(h) * FIN + r]);                           \
            xh1[r] = __float2half2_rn(xr1p[(h) * FIN + r]);                           \
        }                                                                             \
    } while (0)

    // generate As[buf] for K-chunk k0 (head = k0>>7, W1 buffer hb)
#define GEN_A(buf, k0, hb)                                                            \
    do {                                                                              \
        int lc = ((k0) & 127) + colg * 8;                                             \
        const __half* w1p = sW1[hb];                                                  \
        const __half2 zz = __floats2half2_rn(0.f, 0.f);                               \
        _Pragma("unroll")                                                             \
        for (int p = 0; p < 4; p++) {                                                 \
            int c = lc + 2 * p;                                                       \
            __half2 a0 = *(const __half2*)&w1p[9 * HID + c];                          \
            __half2 a1 = a0;                                                          \
            _Pragma("unroll")                                                         \
            for (int r = 0; r < FIN; r++) {                                           \
                __half2 wv = *(const __half2*)&w1p[r * HID + c];                      \
                a0 = __hfma2(xh0[r], wv, a0);                                         \
                a1 = __hfma2(xh1[r], wv, a1);                                         \
            }                                                                         \
            a0 = __hmax2(a0, zz);                                                     \
            a1 = __hmax2(a1, zz);                                                     \
            int cic = colg * 8 + 2 * p;                                               \
            *(__half2*)&As[buf][aswz32(2 * rowg, cic)] = a0;                          \
            *(__half2*)&As[buf][aswz32(2 * rowg + 1, cic)] = a1;                      \
        }                                                                             \
    } while (0)

    // ---- prologue: stage W1 head0 + Bs chunk0, then generate As[0]
    STAGE_W1(0, 0);
    ISSUE_B(0, 0);
    asm volatile("cp.async.commit_group;");
    asm volatile("cp.async.wait_group 0;");
    __syncthreads();
    int curh = 0;
    LOAD_XAGG(0);
    GEN_A(0, 0, 0);
    ISSUE_B(1, 1);
    asm volatile("cp.async.commit_group;");
    __syncthreads();   // As[0] visible

    for (int kt = 0; kt < 32; kt++) {
        int buf = kt & 1;
        // ---- mma over As[buf], Bs[buf]
#pragma unroll
        for (int kk = 0; kk < 32; kk += 16) {
            unsigned a[2][4];
#pragma unroll
            for (int mt = 0; mt < 2; mt++) {
                int r = wm * 32 + mt * 16 + (lane & 15);
                int cc = kk + (lane >> 4) * 8;
                unsigned addr = (unsigned)__cvta_generic_to_shared(&As[buf][aswz32(r, cc)]);
                asm volatile("ldmatrix.sync.aligned.m8n8.x4.shared.b16 {%0,%1,%2,%3}, [%4];"
                             : "=r"(a[mt][0]), "=r"(a[mt][1]), "=r"(a[mt][2]), "=r"(a[mt][3])
                             : "r"(addr));
            }
            unsigned b[8][2];
#pragma unroll
            for (int nt = 0; nt < 8; nt++) {
                int r = kk + (lane & 15);
                int cc = wn * 64 + nt * 8;
                unsigned addr = (unsigned)__cvta_generic_to_shared(&Bs[buf][bswz(r, cc)]);
                asm volatile("ldmatrix.sync.aligned.m8n8.x2.trans.shared.b16 {%0,%1}, [%2];"
                             : "=r"(b[nt][0]), "=r"(b[nt][1]) : "r"(addr));
            }
#pragma unroll
            for (int mt = 0; mt < 2; mt++)
#pragma unroll
                for (int nt = 0; nt < 8; nt++) {
                    asm volatile(
                        "mma.sync.aligned.m16n8k16.row.col.f32.f16.f16.f32 "
                        "{%0,%1,%2,%3}, {%4,%5,%6,%7}, {%8,%9}, {%0,%1,%2,%3};"
                        : "+f"(acc[mt][nt][0]), "+f"(acc[mt][nt][1]),
                          "+f"(acc[mt][nt][2]), "+f"(acc[mt][nt][3])
                        : "r"(a[mt][0]), "r"(a[mt][1]), "r"(a[mt][2]), "r"(a[mt][3]),
                          "r"(b[nt][0]), "r"(b[nt][1]));
                }
        }
        if (kt + 1 < 32) {
            asm volatile("cp.async.wait_group 0;");   // Bs[buf^1] (+W1 stage) arrived
            __syncthreads();                           // all warps done reading [buf]
            if (kt + 2 < 32) ISSUE_B(kt + 2, buf);    // refill freed Bs[buf]
            if ((kt & 3) == 2 && (kt >> 2) + 1 < HEADS)
                STAGE_W1((kt >> 2) + 1, ((kt >> 2) + 1) & 1);  // next head's W1
            asm volatile("cp.async.commit_group;");
            int k0n = (kt + 1) * 32;
            int hn = k0n >> 7;
            if (hn != curh) { curh = hn; LOAD_XAGG(hn); }
            GEN_A(buf ^ 1, k0n, hn & 1);
            __syncthreads();                           // As[buf^1] visible
        }
    }
#undef ISSUE_B
#undef STAGE_W1
#undef LOAD_XAGG
#undef GEN_A

#pragma unroll
    for (int mt = 0; mt < 2; mt++) {
        size_t rbase = m0 + wm * 32 + mt * 16 + (lane >> 2);
#pragma unroll
        for (int nt = 0; nt < 8; nt++) {
            int col = wn * 64 + nt * 8 + (lane & 3) * 2;
            *(__half2*)&g_h2[rbase * HID + col] =
                __floats2half2_rn(acc[mt][nt][0], acc[mt][nt][1]);
            *(__half2*)&g_h2[(rbase + 8) * HID + col] =
                __floats2half2_rn(acc[mt][nt][2], acc[mt][nt][3]);
        }
    }
}

// ---------------- GAT2 attention logits (batched) ----------------
__global__ void __launch_bounds__(256) k_al2(const float* __restrict__ as2,
                                             const float* __restrict__ ad2) {
    int w = threadIdx.x >> 5, lane = threadIdx.x & 31;
    int n = blockIdx.x * 8 + w;
    int t = blockIdx.y;
    if (n >= NN) return;
    uint2 v = *(const uint2*)&g_h2[((size_t)t * NN + n) * HID + lane * 4];
    float2 f0 = __half22float2(*(__half2*)&v.x);
    float2 f1 = __half22float2(*(__half2*)&v.y);
    float4 a = *(const float4*)&as2[lane * 4];
    float4 d = *(const float4*)&ad2[lane * 4];
    float ps = f0.x * a.x + f0.y * a.y + f1.x * a.z + f1.y * a.w;
    float pd = f0.x * d.x + f0.y * d.y + f1.x * d.z + f1.y * d.w;
#pragma unroll
    for (int off = 16; off; off >>= 1) {
        ps += __shfl_xor_sync(FULL, ps, off);
        pd += __shfl_xor_sync(FULL, pd, off);
    }
    if (lane == 0) {
        g_als2[(size_t)t * NN + n] = ps;
        g_ald2[(size_t)t * NN + n] = pd;
    }
}

// ---------------- GAT2 softmax + aggregation (batched) ----------------
__global__ void __launch_bounds__(256) k_agg2(const float* __restrict__ b2) {
    int w = threadIdx.x >> 5, lane = threadIdx.x & 31;
    int n = blockIdx.x * 8 + w;
    int t = blockIdx.y;
    if (n >= NN) return;
    const __half* h2 = g_h2 + (size_t)t * NN * HID;
    const float* als = g_als2 + (size_t)t * NN;
    int start = g_rowptr[n];
    int deg = g_rowptr[n + 1] - start + 1;
    float aldn = g_ald2[(size_t)t * NN + n];

    float sum = 0.f;
    for (int i = lane; i < deg; i += 32) {
        int s = (i < deg - 1) ? g_col[start + i] : n;
        float l = als[s] + aldn;
        l = (l > 0.f) ? l : 0.2f * l;
        sum += __expf(l);
    }
#pragma unroll
    for (int off = 16; off; off >>= 1) sum += __shfl_xor_sync(FULL, sum, off);
    float inv = 1.f / (sum + 1e-16f);

    float a0 = 0.f, a1 = 0.f, a2 = 0.f, a3 = 0.f;
    const int* colp = &g_col[start];
    for (int i = 0; i < deg; i++) {
        int s = (i < deg - 1) ? colp[i] : n;
        float l = als[s] + aldn;
        l = (l > 0.f) ? l : 0.2f * l;
        float al = __expf(l) * inv;
        uint2 v = *(const uint2*)&h2[(size_t)s * HID + lane * 4];
        float2 f0 = __half22float2(*(__half2*)&v.x);
        float2 f1 = __half22float2(*(__half2*)&v.y);
        a0 += al * f0.x; a1 += al * f0.y;
        a2 += al * f1.x; a3 += al * f1.y;
    }
    float4 b = *(const float4*)&b2[lane * 4];
    __half2 p0 = __floats2half2_rn(fmaxf(a0 + b.x, 0.f), fmaxf(a1 + b.y, 0.f));
    __half2 p1 = __floats2half2_rn(fmaxf(a2 + b.z, 0.f), fmaxf(a3 + b.w, 0.f));
    uint2 o;
    o.x = *(unsigned*)&p0; o.y = *(unsigned*)&p1;
    *(uint2*)&g_out2h[((size_t)t * NN + n) * HID + lane * 4] = o;
}

// ---------------- deterministic mean pool (batched) ----------------
__global__ void __launch_bounds__(128) k_pool_a() {
    int c = threadIdx.x, b = blockIdx.x, t = blockIdx.y;
    int n0 = b * PCH, n1 = min(n0 + PCH, NN);
    float s = 0.f;
    for (int n = n0; n < n1; n++)
        s += __half2float(g_out2h[((size_t)t * NN + n) * HID + c]);
    g_partial[((size_t)t * PBLK + b) * HID + c] = s;
}

__global__ void __launch_bounds__(128) k_pool_b() {
    int c = threadIdx.x, t = blockIdx.x;
    float s = 0.f;
    for (int b = 0; b < PBLK; b++) s += g_partial[((size_t)t * PBLK + b) * HID + c];
    g_emb[t * HID + c] = s * (1.0f / NN);
}

// ---------------- GRU + output head ----------------
__global__ void __launch_bounds__(128) k_gru(
    const float* __restrict__ wih, const float* __restrict__ whh,
    const float* __restrict__ bih, const float* __restrict__ bhh,
    const float* __restrict__ wout, const float* __restrict__ bout,
    float* __restrict__ out) {
    int tid = threadIdx.x;
    __shared__ float h[HID], xt[HID];
    __shared__ float red[4];
    h[tid] = 0.f;
    __syncthreads();
    for (int t = 0; t < TT; t++) {
        xt[tid] = g_emb[t * HID + tid];
        __syncthreads();
        float gi[3], gh[3];
#pragma unroll
        for (int q = 0; q < 3; q++) {
            int r = q * HID + tid;
            float s1 = bih[r], s2 = bhh[r];
            const float* wi = &wih[(size_t)r * HID];
            const float* wh = &whh[(size_t)r * HID];
            for (int c = 0; c < HID; c++) {
                s1 += xt[c] * wi[c];
                s2 += h[c] * wh[c];
            }
            gi[q] = s1;
            gh[q] = s2;
        }
        float r  = 1.f / (1.f + __expf(-(gi[0] + gh[0])));
        float z  = 1.f / (1.f + __expf(-(gi[1] + gh[1])));
        float nn = tanhf(gi[2] + r * gh[2]);
        float hn = (1.f - z) * nn + z * h[tid];
        __syncthreads();
        h[tid] = hn;
        __syncthreads();
        float v = hn * wout[tid];
        int lane = tid & 31, w = tid >> 5;
        for (int o = 16; o; o >>= 1) v += __shfl_down_sync(FULL, v, o);
        if (lane == 0) red[w] = v;
        __syncthreads();
        if (tid == 0) out[t] = red[0] + red[1] + red[2] + red[3] + bout[0];
        __syncthreads();
    }
}

// ---------------- launch ----------------
extern "C" void kernel_launch(void* const* d_in, const int* in_sizes, int n_in,
                              void* d_out, int out_size) {
    const float* x    = (const float*)d_in[0];
    const void*  ei   = d_in[1];
    const float* W1   = (const float*)d_in[2];
    const float* as1  = (const float*)d_in[3];
    const float* ad1  = (const float*)d_in[4];
    const float* b1   = (const float*)d_in[5];
    const float* W2   = (const float*)d_in[6];
    const float* as2  = (const float*)d_in[7];
    const float* ad2  = (const float*)d_in[8];
    const float* b2   = (const float*)d_in[9];
    const float* wih  = (const float*)d_in[10];
    const float* whh  = (const float*)d_in[11];
    const float* bih  = (const float*)d_in[12];
    const float* bhh  = (const float*)d_in[13];
    const float* wout = (const float*)d_in[14];
    const float* bout = (const float*)d_in[15];
    float* out = (float*)d_out;

    k_zc<<<(NN + 255) / 256, 256>>>();
    k_count<<<(EE + 255) / 256, 256>>>(ei);
    k_prep<<<(D1 * HID + 255) / 256, 256>>>(W2, W1, as1, ad1, b1);
    k_logits1<<<(TT * NN + 255) / 256, 256>>>(x);
    k_scan<<<1, 1024>>>();
    k_fill<<<(EE + 255) / 256, 256>>>(ei);
    k_agg1x<<<dim3((NN + 7) / 8, TT), 256>>>(x);
    k_gemmf<<<MM / 128, 256>>>();
    k_al2<<<dim3((NN + 7) / 8, TT), 256>>>(as2, ad2);
    k_agg2<<<dim3((NN + 7) / 8, TT), 256>>>(b2);
    k_pool_a<<<dim3(PBLK, TT), 128>>>();
    k_pool_b<<<TT, 128>>>();
    k_gru<<<1, 128>>>(wih, whh, bih, bhh, wout, bout, out);
}

// round 16
// speedup vs baseline: 2.2832x; 1.5065x over previous
#include <cuda_runtime.h>
#include <cuda_fp16.h>

#define NN 20000
#define EE 320000
#define TT 16
#define FIN 9
#define HID 128
#define HEADS 8
#define D1 1024          // HEADS*HID
#define MM (TT * NN)     // 320000 flat rows
#define PBLK 160
#define PCH 125
#define FULL 0xffffffffu

// ---------------- static device scratch ----------------
__device__ int   g_is64;
__device__ int   g_cnt[NN];
__device__ int   g_rowptr[NN + 1];
__device__ int   g_cursor[NN];
__device__ int   g_col[EE];
__device__ float g_w1as[FIN * HEADS];
__device__ float g_w1ad[FIN * HEADS];
__device__ float g_als1[(size_t)TT * NN * HEADS];
__device__ float g_ald1[(size_t)TT * NN * HEADS];
__device__ float g_xagg[(size_t)TT * NN * 72];
__device__ __align__(16) __half g_W1b[HEADS * 10 * HID];   // per-head [10][128]: rows 0-8 = W1, row 9 = b1
__device__ __align__(16) __half g_W2h[D1 * HID];
__device__ __align__(16) __half g_h2[(size_t)MM * HID];
__device__ float g_als2[(size_t)TT * NN];
__device__ float g_ald2[(size_t)TT * NN];
__device__ __align__(16) __half g_out2h[(size_t)TT * NN * HID];
__device__ float g_partial[(size_t)TT * PBLK * HID];
__device__ float g_emb[TT * HID];

// ---------------- CSR setup ----------------
__global__ void k_zc() {
    int i = blockIdx.x * blockDim.x + threadIdx.x;
    if (i < NN) g_cnt[i] = 0;
}

__global__ void k_count(const void* __restrict__ ei) {
    int e = blockIdx.x * blockDim.x + threadIdx.x;
    if (e >= EE) return;
    const long long* p64 = (const long long*)ei;
    int ok = 1;
#pragma unroll
    for (int q = 0; q < 8; q++) {
        long long v = p64[q];
        if (v < 0 || v >= NN) ok = 0;
    }
    if (e == 0) g_is64 = ok;
    int d = ok ? (int)p64[(size_t)EE + e] : ((const int*)ei)[(size_t)EE + e];
    if (d >= 0 && d < NN) atomicAdd(&g_cnt[d], 1);
}

__global__ void k_scan() {
    __shared__ int part[1024];
    int tid = threadIdx.x;
    const int CH = (NN + 1023) / 1024;
    int base = tid * CH;
    int s = 0;
    for (int i = 0; i < CH; i++) {
        int idx = base + i;
        if (idx < NN) s += g_cnt[idx];
    }
    part[tid] = s;
    __syncthreads();
    for (int off = 1; off < 1024; off <<= 1) {
        int v = (tid >= off) ? part[tid - off] : 0;
        __syncthreads();
        part[tid] += v;
        __syncthreads();
    }
    int run = part[tid] - s;
    for (int i = 0; i < CH; i++) {
        int idx = base + i;
        if (idx < NN) {
            g_rowptr[idx] = run;
            g_cursor[idx] = run;
            run += g_cnt[idx];
        }
    }
    if (tid == 1023) g_rowptr[NN] = part[1023];
}

__global__ void k_fill(const void* __restrict__ ei) {
    int e = blockIdx.x * blockDim.x + threadIdx.x;
    if (e < EE) {
        int is64 = g_is64;
        int s = is64 ? (int)((const long long*)ei)[e] : ((const int*)ei)[e];
        int d = is64 ? (int)((const long long*)ei)[(size_t)EE + e]
                     : ((const int*)ei)[(size_t)EE + e];
        if (s >= 0 && s < NN && d >= 0 && d < NN) {
            int p = atomicAdd(&g_cursor[d], 1);
            g_col[p] = s;
        }
    }
}

// ---------------- prep: W2 fp16, W1+b1 per-head fp16, W1a projections ----------------
__global__ void k_prep(const float* __restrict__ W2, const float* __restrict__ W1,
                       const float* __restrict__ as1, const float* __restrict__ ad1,
                       const float* __restrict__ b1) {
    int i = blockIdx.x * blockDim.x + threadIdx.x;
    if (i < D1 * HID) g_W2h[i] = __float2half(W2[i]);
    if (i < HEADS * 10 * HID) {
        int h = i / (10 * HID);
        int rem = i - h * 10 * HID;
        int r = rem >> 7, c = rem & 127;
        g_W1b[i] = __float2half((r < 9) ? W1[r * D1 + h * HID + c] : b1[h * HID + c]);
    }
    if (blockIdx.x == 0 && threadIdx.x < FIN * HEADS) {
        int r = threadIdx.x / HEADS, h = threadIdx.x % HEADS;
        float s1 = 0.f, s2 = 0.f;
        for (int c = 0; c < HID; c++) {
            float wv = W1[r * D1 + h * HID + c];
            s1 += wv * as1[h * HID + c];
            s2 += wv * ad1[h * HID + c];
        }
        g_w1as[threadIdx.x] = s1;
        g_w1ad[threadIdx.x] = s2;
    }
}

// ---------------- GAT1 attention logits for all (t,n) ----------------
__global__ void __launch_bounds__(256) k_logits1(const float* __restrict__ x) {
    int id = blockIdx.x * blockDim.x + threadIdx.x;
    if (id >= TT * NN) return;
    float xv[FIN];
#pragma unroll
    for (int r = 0; r < FIN; r++) xv[r] = x[(size_t)id * FIN + r];
#pragma unroll
    for (int h = 0; h < HEADS; h++) {
        float s1 = 0.f, s2 = 0.f;
#pragma unroll
        for (int r = 0; r < FIN; r++) {
            s1 += xv[r] * g_w1as[r * HEADS + h];
            s2 += xv[r] * g_w1ad[r * HEADS + h];
        }
        g_als1[(size_t)id * HEADS + h] = s1;
        g_ald1[(size_t)id * HEADS + h] = s2;
    }
}

// ---------------- GAT1 aggregation, raw feature space (warp-per-node) ----------------
__global__ void __launch_bounds__(256) k_agg1x(const float* __restrict__ x) {
    int w = threadIdx.x >> 5, lane = threadIdx.x & 31;
    int n = blockIdx.x * 8 + w;
    int t = blockIdx.y;
    if (n >= NN) return;
    const float* als = g_als1 + (size_t)t * NN * HEADS;
    const float* ald = g_ald1 + (size_t)t * NN * HEADS;
    const float* xt  = x + (size_t)t * NN * FIN;
    int start = g_rowptr[n];
    int deg = g_rowptr[n + 1] - start + 1;

    int h8 = lane & 7;
    float aldh = ald[n * HEADS + h8];

    float sum = 0.f;
    for (int i = lane >> 3; i < deg; i += 4) {
        int s = (i < deg - 1) ? g_col[start + i] : n;
        float l = als[s * HEADS + h8] + aldh;
        l = (l > 0.f) ? l : 0.2f * l;
        sum += __expf(l);
    }
    sum += __shfl_xor_sync(FULL, sum, 8);
    sum += __shfl_xor_sync(FULL, sum, 16);
    float inv = 1.f / (sum + 1e-16f);

    int h = lane >> 2, q = lane & 3;
    float invh = __shfl_sync(FULL, inv, h);
    float a0 = 0.f, a1 = 0.f, a2 = 0.f;
    const int* colp = &g_col[start];
    for (int i = 0; i < deg; i++) {
        int s = (i < deg - 1) ? colp[i] : n;
        float l = als[s * HEADS + h8] + aldh;
        l = (l > 0.f) ? l : 0.2f * l;
        float e = __expf(l);
        float alpha = __shfl_sync(FULL, e, h) * invh;
        const float* xs = &xt[(size_t)s * FIN];
        a0 += alpha * xs[q];
        a1 += alpha * xs[q + 4];
        if (q == 0) a2 += alpha * xs[8];
    }
    float* dst = &g_xagg[((size_t)t * NN + n) * 72 + h * FIN];
    dst[q] = a0;
    dst[q + 4] = a1;
    if (q == 0) dst[8] = a2;
}

// ---------------- fused TC GEMM: h2 = relu(xagg@W1+b1) @ W2, A generated in-kernel ----------------
__device__ __forceinline__ int aswz32(int row, int col) {
    int chunk = (col >> 3) & 3;
    int sw = chunk ^ ((row >> 1) & 3);
    return row * 32 + sw * 8 + (col & 7);
}
__device__ __forceinline__ int bswz(int row, int col) {
    int chunk = col >> 3;
    int sw = (chunk & 8) | ((chunk ^ row) & 7);
    return row * 128 + sw * 8 + (col & 7);
}

__global__ void __launch_bounds__(256) k_gemmf() {
    __shared__ __half As[2][128 * 32];       // 16 KB
    __shared__ __half Bs[2][32 * 128];       // 16 KB
    __shared__ __half sW1[2][10 * HID];      // 5 KB
    int tid = threadIdx.x;
    int lane = tid & 31, w = tid >> 5;
    int wm = w & 3, wn = w >> 2;
    size_t m0 = (size_t)blockIdx.x * 128;

    float acc[2][8][4];
#pragma unroll
    for (int mt = 0; mt < 2; mt++)
#pragma unroll
        for (int nt = 0; nt < 8; nt++)
#pragma unroll
            for (int q = 0; q < 4; q++) acc[mt][nt][q] = 0.f;

    int brow = tid >> 3;
    int bc0 = (tid & 7) * 2;
    int rowg = tid >> 2;
    int colg = tid & 3;
    const float* xr0p = &g_xagg[(m0 + 2 * rowg) * 72];
    const float* xr1p = xr0p + 72;

#define ISSUE_B(kt, buf)                                                              \
    do {                                                                              \
        _Pragma("unroll")                                                             \
        for (int c = 0; c < 2; c++) {                                                 \
            int ch = bc0 + c;                                                         \
            unsigned d_ = (unsigned)__cvta_generic_to_shared(                         \
                &Bs[buf][bswz(brow, ch * 8)]);                                        \
            const __half* s_ = &g_W2h[(size_t)((kt) * 32 + brow) * HID + ch * 8];     \
            asm volatile("cp.async.ca.shared.global [%0], [%1], 16;" ::               \
                         "r"(d_), "l"(s_));                                           \
        }                                                                             \
    } while (0)

#define STAGE_W1(h, hb)                                                               \
    do {                                                                              \
        if (tid < 160) {                                                              \
            unsigned d_ = (unsigned)__cvta_generic_to_shared(&sW1[hb][tid * 8]);      \
            const __half* s_ = g_W1b + (h) * (10 * HID) + tid * 8;                    \
            asm volatile("cp.async.ca.shared.global [%0], [%1], 16;" ::               \
                         "r"(d_), "l"(s_));                                           \
        }                                                                             \
    } while (0)

    __half2 xh0[FIN], xh1[FIN];
#define LOAD_XAGG(h)                                                                  \
    do {                                                                              \
        _Pragma("unroll")                                                             \
        for (int r = 0; r < FIN; r++) {                                               \
            xh0[r] = __float2half2_rn(xr0p[(h) * FIN + r]);                           \
            xh1[r] = __float2half2_rn(xr1p[(h) * FIN + r]);                           \
        }                                                                             \
    } while (0)

#define GEN_A(buf, k0, hb)                                                            \
    do {                                                                              \
        int lc = ((k0) & 127) + colg * 8;                                             \
        const __half* w1p = sW1[hb];                                                  \
        const __half2 zz = __floats2half2_rn(0.f, 0.f);                               \
        _Pragma("unroll")                                                             \
        for (int p = 0; p < 4; p++) {                                                 \
            int c = lc + 2 * p;                                                       \
            __half2 a0 = *(const __half2*)&w1p[9 * HID + c];                          \
            __half2 a1 = a0;                                                          \
            _Pragma("unroll")                                                         \
            for (int r = 0; r < FIN; r++) {                                           \
                __half2 wv = *(const __half2*)&w1p[r * HID + c];                      \
                a0 = __hfma2(xh0[r], wv, a0);                                         \
                a1 = __hfma2(xh1[r], wv, a1);                                         \
            }                                                                         \
            a0 = __hmax2(a0, zz);                                                     \
            a1 = __hmax2(a1, zz);                                                     \
            int cic = colg * 8 + 2 * p;                                               \
            *(__half2*)&As[buf][aswz32(2 * rowg, cic)] = a0;                          \
            *(__half2*)&As[buf][aswz32(2 * rowg + 1, cic)] = a1;                      \
        }                                                                             \
    } while (0)

    STAGE_W1(0, 0);
    ISSUE_B(0, 0);
    asm volatile("cp.async.commit_group;");
    asm volatile("cp.async.wait_group 0;");
    __syncthreads();
    int curh = 0;
    LOAD_XAGG(0);
    GEN_A(0, 0, 0);
    ISSUE_B(1, 1);
    asm volatile("cp.async.commit_group;");
    __syncthreads();

    for (int kt = 0; kt < 32; kt++) {
        int buf = kt & 1;
#pragma unroll
        for (int kk = 0; kk < 32; kk += 16) {
            unsigned a[2][4];
#pragma unroll
            for (int mt = 0; mt < 2; mt++) {
                int r = wm * 32 + mt * 16 + (lane & 15);
                int cc = kk + (lane >> 4) * 8;
                unsigned addr = (unsigned)__cvta_generic_to_shared(&As[buf][aswz32(r, cc)]);
                asm volatile("ldmatrix.sync.aligned.m8n8.x4.shared.b16 {%0,%1,%2,%3}, [%4];"
                             : "=r"(a[mt][0]), "=r"(a[mt][1]), "=r"(a[mt][2]), "=r"(a[mt][3])
                             : "r"(addr));
            }
            unsigned b[8][2];
#pragma unroll
            for (int nt = 0; nt < 8; nt++) {
                int r = kk + (lane & 15);
                int cc = wn * 64 + nt * 8;
                unsigned addr = (unsigned)__cvta_generic_to_shared(&Bs[buf][bswz(r, cc)]);
                asm volatile("ldmatrix.sync.aligned.m8n8.x2.trans.shared.b16 {%0,%1}, [%2];"
                             : "=r"(b[nt][0]), "=r"(b[nt][1]) : "r"(addr));
            }
#pragma unroll
            for (int mt = 0; mt < 2; mt++)
#pragma unroll
                for (int nt = 0; nt < 8; nt++) {
                    asm volatile(
                        "mma.sync.aligned.m16n8k16.row.col.f32.f16.f16.f32 "
                        "{%0,%1,%2,%3}, {%4,%5,%6,%7}, {%8,%9}, {%0,%1,%2,%3};"
                        : "+f"(acc[mt][nt][0]), "+f"(acc[mt][nt][1]),
                          "+f"(acc[mt][nt][2]), "+f"(acc[mt][nt][3])
                        : "r"(a[mt][0]), "r"(a[mt][1]), "r"(a[mt][2]), "r"(a[mt][3]),
                          "r"(b[nt][0]), "r"(b[nt][1]));
                }
        }
        if (kt + 1 < 32) {
            asm volatile("cp.async.wait_group 0;");
            __syncthreads();
            if (kt + 2 < 32) ISSUE_B(kt + 2, buf);
            if ((kt & 3) == 2 && (kt >> 2) + 1 < HEADS)
                STAGE_W1((kt >> 2) + 1, ((kt >> 2) + 1) & 1);
            asm volatile("cp.async.commit_group;");
            int k0n = (kt + 1) * 32;
            int hn = k0n >> 7;
            if (hn != curh) { curh = hn; LOAD_XAGG(hn); }
            GEN_A(buf ^ 1, k0n, hn & 1);
            __syncthreads();
        }
    }
#undef ISSUE_B
#undef STAGE_W1
#undef LOAD_XAGG
#undef GEN_A

#pragma unroll
    for (int mt = 0; mt < 2; mt++) {
        size_t rbase = m0 + wm * 32 + mt * 16 + (lane >> 2);
#pragma unroll
        for (int nt = 0; nt < 8; nt++) {
            int col = wn * 64 + nt * 8 + (lane & 3) * 2;
            *(__half2*)&g_h2[rbase * HID + col] =
                __floats2half2_rn(acc[mt][nt][0], acc[mt][nt][1]);
            *(__half2*)&g_h2[(rbase + 8) * HID + col] =
                __floats2half2_rn(acc[mt][nt][2], acc[mt][nt][3]);
        }
    }
}

// ---------------- GAT2 attention logits (batched) ----------------
__global__ void __launch_bounds__(256) k_al2(const float* __restrict__ as2,
                                             const float* __restrict__ ad2) {
    int w = threadIdx.x >> 5, lane = threadIdx.x & 31;
    int n = blockIdx.x * 8 + w;
    int t = blockIdx.y;
    if (n >= NN) return;
    uint2 v = *(const uint2*)&g_h2[((size_t)t * NN + n) * HID + lane * 4];
    float2 f0 = __half22float2(*(__half2*)&v.x);
    float2 f1 = __half22float2(*(__half2*)&v.y);
    float4 a = *(const float4*)&as2[lane * 4];
    float4 d = *(const float4*)&ad2[lane * 4];
    float ps = f0.x * a.x + f0.y * a.y + f1.x * a.z + f1.y * a.w;
    float pd = f0.x * d.x + f0.y * d.y + f1.x * d.z + f1.y * d.w;
#pragma unroll
    for (int off = 16; off; off >>= 1) {
        ps += __shfl_xor_sync(FULL, ps, off);
        pd += __shfl_xor_sync(FULL, pd, off);
    }
    if (lane == 0) {
        g_als2[(size_t)t * NN + n] = ps;
        g_ald2[(size_t)t * NN + n] = pd;
    }
}

// ---------------- GAT2 softmax + aggregation (batched) ----------------
__global__ void __launch_bounds__(256) k_agg2(const float* __restrict__ b2) {
    int w = threadIdx.x >> 5, lane = threadIdx.x & 31;
    int n = blockIdx.x * 8 + w;
    int t = blockIdx.y;
    if (n >= NN) return;
    const __half* h2 = g_h2 + (size_t)t * NN * HID;
    const float* als = g_als2 + (size_t)t * NN;
    int start = g_rowptr[n];
    int deg = g_rowptr[n + 1] - start + 1;
    float aldn = g_ald2[(size_t)t * NN + n];

    float sum = 0.f;
    for (int i = lane; i < deg; i += 32) {
        int s = (i < deg - 1) ? g_col[start + i] : n;
        float l = als[s] + aldn;
        l = (l > 0.f) ? l : 0.2f * l;
        sum += __expf(l);
    }
#pragma unroll
    for (int off = 16; off; off >>= 1) sum += __shfl_xor_sync(FULL, sum, off);
    float inv = 1.f / (sum + 1e-16f);

    float a0 = 0.f, a1 = 0.f, a2 = 0.f, a3 = 0.f;
    const int* colp = &g_col[start];
    for (int i = 0; i < deg; i++) {
        int s = (i < deg - 1) ? colp[i] : n;
        float l = als[s] + aldn;
        l = (l > 0.f) ? l : 0.2f * l;
        float al = __expf(l) * inv;
        uint2 v = *(const uint2*)&h2[(size_t)s * HID + lane * 4];
        float2 f0 = __half22float2(*(__half2*)&v.x);
        float2 f1 = __half22float2(*(__half2*)&v.y);
        a0 += al * f0.x; a1 += al * f0.y;
        a2 += al * f1.x; a3 += al * f1.y;
    }
    float4 b = *(const float4*)&b2[lane * 4];
    __half2 p0 = __floats2half2_rn(fmaxf(a0 + b.x, 0.f), fmaxf(a1 + b.y, 0.f));
    __half2 p1 = __floats2half2_rn(fmaxf(a2 + b.z, 0.f), fmaxf(a3 + b.w, 0.f));
    uint2 o;
    o.x = *(unsigned*)&p0; o.y = *(unsigned*)&p1;
    *(uint2*)&g_out2h[((size_t)t * NN + n) * HID + lane * 4] = o;
}

// ---------------- deterministic mean pool (batched) ----------------
__global__ void __launch_bounds__(128) k_pool_a() {
    int c = threadIdx.x, b = blockIdx.x, t = blockIdx.y;
    int n0 = b * PCH, n1 = min(n0 + PCH, NN);
    float s = 0.f;
    for (int n = n0; n < n1; n++)
        s += __half2float(g_out2h[((size_t)t * NN + n) * HID + c]);
    g_partial[((size_t)t * PBLK + b) * HID + c] = s;
}

__global__ void __launch_bounds__(128) k_pool_b() {
    int c = threadIdx.x, t = blockIdx.x;
    float s = 0.f;
    for (int b = 0; b < PBLK; b++) s += g_partial[((size_t)t * PBLK + b) * HID + c];
    g_emb[t * HID + c] = s * (1.0f / NN);
}

// ---------------- GRU + output head: 384 threads, one gate-row per thread,
// full fp32, w-row held in 128 registers (no global loads in the recurrence) ----------------
__global__ void __launch_bounds__(384) k_gru3(
    const float* __restrict__ wih, const float* __restrict__ whh,
    const float* __restrict__ bih, const float* __restrict__ bhh,
    const float* __restrict__ wout, const float* __restrict__ bout,
    float* __restrict__ out) {
    __shared__ float semb[TT * HID];     // 8 KB
    __shared__ float sgi[TT * 384];      // 24.5 KB
    __shared__ float sgh[384];
    __shared__ float sh[HID + 4];        // h state (+pad)
    __shared__ float red[4];
    int tid = threadIdx.x;               // gate-row 0..383

    for (int i = tid; i < TT * HID; i += 384) semb[i] = g_emb[i];

    float wreg[HID];                     // 128 registers
    // ---- stage 1: gi = emb @ w_ih^T + b_ih
    {
        const float* ws = &wih[(size_t)tid * HID];
#pragma unroll 16
        for (int i = 0; i < HID; i++) wreg[i] = ws[i];
        float bi = bih[tid];
        __syncthreads();                 // semb ready
        for (int t = 0; t < TT; t++) {
            const float* e = &semb[t * HID];
            float s = bi;
#pragma unroll 16
            for (int i = 0; i < HID; i++) s += wreg[i] * e[i];
            sgi[t * 384 + tid] = s;
        }
    }
    // ---- stage 2: recurrence with w_hh in registers
    {
        const float* ws = &whh[(size_t)tid * HID];
#pragma unroll 16
        for (int i = 0; i < HID; i++) wreg[i] = ws[i];
    }
    float bh = bhh[tid];
    if (tid < HID) sh[tid] = 0.f;
    __syncthreads();                     // sgi + sh ready

    for (int t = 0; t < TT; t++) {
        float s = bh;
#pragma unroll 16
        for (int i = 0; i < HID; i++) s += wreg[i] * sh[i];
        sgh[tid] = s;
        __syncthreads();                 // sgh visible; all sh reads done

        if (tid < HID) {
            int j = tid;
            float grv = sgi[t * 384 + j]       + sgh[j];
            float gzv = sgi[t * 384 + 128 + j] + sgh[128 + j];
            float gnv = sgi[t * 384 + 256 + j];
            float ghn = sgh[256 + j];
            float rr = 1.f / (1.f + __expf(-grv));
            float zz = 1.f / (1.f + __expf(-gzv));
            float nn = tanhf(gnv + rr * ghn);
            float hn = (1.f - zz) * nn + zz * sh[j];
            sh[j] = hn;
            float v = hn * wout[j];
#pragma unroll
            for (int o = 16; o; o >>= 1) v += __shfl_down_sync(FULL, v, o);
            if ((tid & 31) == 0) red[tid >> 5] = v;
        }
        __syncthreads();                 // new sh + red visible
        if (tid == 0) out[t] = red[0] + red[1] + red[2] + red[3] + bout[0];
    }
}

// ---------------- launch ----------------
extern "C" void kernel_launch(void* const* d_in, const int* in_sizes, int n_in,
                              void* d_out, int out_size) {
    const float* x    = (const float*)d_in[0];
    const void*  ei   = d_in[1];
    const float* W1   = (const float*)d_in[2];
    const float* as1  = (const float*)d_in[3];
    const float* ad1  = (const float*)d_in[4];
    const float* b1   = (const float*)d_in[5];
    const float* W2   = (const float*)d_in[6];
    const float* as2  = (const float*)d_in[7];
    const float* ad2  = (const float*)d_in[8];
    const float* b2   = (const float*)d_in[9];
    const float* wih  = (const float*)d_in[10];
    const float* whh  = (const float*)d_in[11];
    const float* bih  = (const float*)d_in[12];
    const float* bhh  = (const float*)d_in[13];
    const float* wout = (const float*)d_in[14];
    const float* bout = (const float*)d_in[15];
    float* out = (float*)d_out;

    k_zc<<<(NN + 255) / 256, 256>>>();
    k_count<<<(EE + 255) / 256, 256>>>(ei);
    k_prep<<<(D1 * HID + 255) / 256, 256>>>(W2, W1, as1, ad1, b1);
    k_logits1<<<(TT * NN + 255) / 256, 256>>>(x);
    k_scan<<<1, 1024>>>();
    k_fill<<<(EE + 255) / 256, 256>>>(ei);
    k_agg1x<<<dim3((NN + 7) / 8, TT), 256>>>(x);
    k_gemmf<<<MM / 128, 256>>>();
    k_al2<<<dim3((NN + 7) / 8, TT), 256>>>(as2, ad2);
    k_agg2<<<dim3((NN + 7) / 8, TT), 256>>>(b2);
    k_pool_a<<<dim3(PBLK, TT), 128>>>();
    k_pool_b<<<TT, 128>>>();
    k_gru3<<<1, 384>>>(wih, whh, bih, bhh, wout, bout, out);
}

// round 17
// speedup vs baseline: 2.4446x; 1.0707x over previous
#include <cuda_runtime.h>
#include <cuda_fp16.h>

#define NN 20000
#define EE 320000
#define TT 16
#define FIN 9
#define HID 128
#define HEADS 8
#define D1 1024          // HEADS*HID
#define MM (TT * NN)     // 320000 flat rows
#define PBLK 160
#define PCH 125
#define FULL 0xffffffffu

// ---------------- static device scratch ----------------
__device__ int   g_is64;
__device__ int   g_cnt[NN];
__device__ int   g_rowptr[NN + 1];
__device__ int   g_cursor[NN];
__device__ int   g_col[EE];
__device__ float g_w1as[FIN * HEADS];
__device__ float g_w1ad[FIN * HEADS];
__device__ float g_als1[(size_t)TT * NN * HEADS];
__device__ float g_ald1[(size_t)TT * NN * HEADS];
__device__ float g_xagg[(size_t)TT * NN * 72];
__device__ __align__(16) __half g_W1b[HEADS * 10 * HID];   // per-head [10][128]: rows 0-8 = W1, row 9 = b1
__device__ __align__(16) __half g_W2h[D1 * HID];
__device__ __align__(16) __half g_h2[(size_t)MM * HID];
__device__ float g_als2[(size_t)TT * NN];
__device__ float g_ald2[(size_t)TT * NN];
__device__ __align__(16) __half g_out2h[(size_t)TT * NN * HID];
__device__ float g_partial[(size_t)TT * PBLK * HID];
__device__ float g_emb[TT * HID];

// ---------------- CSR setup ----------------
__global__ void k_zc() {
    int i = blockIdx.x * blockDim.x + threadIdx.x;
    if (i < NN) g_cnt[i] = 0;
}

__global__ void k_count(const void* __restrict__ ei) {
    int e = blockIdx.x * blockDim.x + threadIdx.x;
    if (e >= EE) return;
    const long long* p64 = (const long long*)ei;
    int ok = 1;
#pragma unroll
    for (int q = 0; q < 8; q++) {
        long long v = p64[q];
        if (v < 0 || v >= NN) ok = 0;
    }
    if (e == 0) g_is64 = ok;
    int d = ok ? (int)p64[(size_t)EE + e] : ((const int*)ei)[(size_t)EE + e];
    if (d >= 0 && d < NN) atomicAdd(&g_cnt[d], 1);
}

__global__ void k_scan() {
    __shared__ int part[1024];
    int tid = threadIdx.x;
    const int CH = (NN + 1023) / 1024;
    int base = tid * CH;
    int s = 0;
    for (int i = 0; i < CH; i++) {
        int idx = base + i;
        if (idx < NN) s += g_cnt[idx];
    }
    part[tid] = s;
    __syncthreads();
    for (int off = 1; off < 1024; off <<= 1) {
        int v = (tid >= off) ? part[tid - off] : 0;
        __syncthreads();
        part[tid] += v;
        __syncthreads();
    }
    int run = part[tid] - s;
    for (int i = 0; i < CH; i++) {
        int idx = base + i;
        if (idx < NN) {
            g_rowptr[idx] = run;
            g_cursor[idx] = run;
            run += g_cnt[idx];
        }
    }
    if (tid == 1023) g_rowptr[NN] = part[1023];
}

__global__ void k_fill(const void* __restrict__ ei) {
    int e = blockIdx.x * blockDim.x + threadIdx.x;
    if (e < EE) {
        int is64 = g_is64;
        int s = is64 ? (int)((const long long*)ei)[e] : ((const int*)ei)[e];
        int d = is64 ? (int)((const long long*)ei)[(size_t)EE + e]
                     : ((const int*)ei)[(size_t)EE + e];
        if (s >= 0 && s < NN && d >= 0 && d < NN) {
            int p = atomicAdd(&g_cursor[d], 1);
            g_col[p] = s;
        }
    }
}

// ---------------- prep: W2 fp16, W1+b1 per-head fp16, W1a projections ----------------
__global__ void k_prep(const float* __restrict__ W2, const float* __restrict__ W1,
                       const float* __restrict__ as1, const float* __restrict__ ad1,
                       const float* __restrict__ b1) {
    int i = blockIdx.x * blockDim.x + threadIdx.x;
    if (i < D1 * HID) g_W2h[i] = __float2half(W2[i]);
    if (i < HEADS * 10 * HID) {
        int h = i / (10 * HID);
        int rem = i - h * 10 * HID;
        int r = rem >> 7, c = rem & 127;
        g_W1b[i] = __float2half((r < 9) ? W1[r * D1 + h * HID + c] : b1[h * HID + c]);
    }
    if (blockIdx.x == 0 && threadIdx.x < FIN * HEADS) {
        int r = threadIdx.x / HEADS, h = threadIdx.x % HEADS;
        float s1 = 0.f, s2 = 0.f;
        for (int c = 0; c < HID; c++) {
            float wv = W1[r * D1 + h * HID + c];
            s1 += wv * as1[h * HID + c];
            s2 += wv * ad1[h * HID + c];
        }
        g_w1as[threadIdx.x] = s1;
        g_w1ad[threadIdx.x] = s2;
    }
}

// ---------------- GAT1 attention logits for all (t,n) ----------------
__global__ void __launch_bounds__(256) k_logits1(const float* __restrict__ x) {
    int id = blockIdx.x * blockDim.x + threadIdx.x;
    if (id >= TT * NN) return;
    float xv[FIN];
#pragma unroll
    for (int r = 0; r < FIN; r++) xv[r] = x[(size_t)id * FIN + r];
#pragma unroll
    for (int h = 0; h < HEADS; h++) {
        float s1 = 0.f, s2 = 0.f;
#pragma unroll
        for (int r = 0; r < FIN; r++) {
            s1 += xv[r] * g_w1as[r * HEADS + h];
            s2 += xv[r] * g_w1ad[r * HEADS + h];
        }
        g_als1[(size_t)id * HEADS + h] = s1;
        g_ald1[(size_t)id * HEADS + h] = s2;
    }
}

// ---------------- GAT1 aggregation, raw feature space (warp-per-node) ----------------
__global__ void __launch_bounds__(256) k_agg1x(const float* __restrict__ x) {
    int w = threadIdx.x >> 5, lane = threadIdx.x & 31;
    int n = blockIdx.x * 8 + w;
    int t = blockIdx.y;
    if (n >= NN) return;
    const float* als = g_als1 + (size_t)t * NN * HEADS;
    const float* ald = g_ald1 + (size_t)t * NN * HEADS;
    const float* xt  = x + (size_t)t * NN * FIN;
    int start = g_rowptr[n];
    int deg = g_rowptr[n + 1] - start + 1;

    int h8 = lane & 7;
    float aldh = ald[n * HEADS + h8];

    float sum = 0.f;
    for (int i = lane >> 3; i < deg; i += 4) {
        int s = (i < deg - 1) ? g_col[start + i] : n;
        float l = als[s * HEADS + h8] + aldh;
        l = (l > 0.f) ? l : 0.2f * l;
        sum += __expf(l);
    }
    sum += __shfl_xor_sync(FULL, sum, 8);
    sum += __shfl_xor_sync(FULL, sum, 16);
    float inv = 1.f / (sum + 1e-16f);

    int h = lane >> 2, q = lane & 3;
    float invh = __shfl_sync(FULL, inv, h);
    float a0 = 0.f, a1 = 0.f, a2 = 0.f;
    const int* colp = &g_col[start];
    for (int i = 0; i < deg; i++) {
        int s = (i < deg - 1) ? colp[i] : n;
        float l = als[s * HEADS + h8] + aldh;
        l = (l > 0.f) ? l : 0.2f * l;
        float e = __expf(l);
        float alpha = __shfl_sync(FULL, e, h) * invh;
        const float* xs = &xt[(size_t)s * FIN];
        a0 += alpha * xs[q];
        a1 += alpha * xs[q + 4];
        if (q == 0) a2 += alpha * xs[8];
    }
    float* dst = &g_xagg[((size_t)t * NN + n) * 72 + h * FIN];
    dst[q] = a0;
    dst[q + 4] = a1;
    if (q == 0) dst[8] = a2;
}

// ---------------- tensor-gen GEMM: h2 = relu(xagg@W1+b1) @ W2 ----------------
// A-fragments produced by gen-mma entirely in registers; only B (W2) uses smem.
__device__ __forceinline__ int bswz(int row, int col) {
    int chunk = col >> 3;
    int sw = (chunk & 8) | ((chunk ^ row) & 7);
    return row * 128 + sw * 8 + (col & 7);
}
__device__ __forceinline__ unsigned h2u(__half2 v) { return *(unsigned*)&v; }

__global__ void __launch_bounds__(256) k_gemmt() {
    __shared__ __half Bs[2][32 * 128];   // 16 KB double-buffered W2 tiles
    int tid = threadIdx.x;
    int lane = tid & 31, w = tid >> 5;
    int wm = w & 3, wn = w >> 2;
    size_t m0 = (size_t)blockIdx.x * 128;

    float acc[2][8][4];
#pragma unroll
    for (int mt = 0; mt < 2; mt++)
#pragma unroll
        for (int nt = 0; nt < 8; nt++)
#pragma unroll
            for (int q = 0; q < 4; q++) acc[mt][nt][q] = 0.f;

    int brow = tid >> 3;
    int bc0 = (tid & 7) * 2;
    int r4 = lane >> 2;          // 0..7
    int kg = (lane & 3) * 2;     // 0,2,4,6

    unsigned agen[2][4];         // per-head A_gen fragments (xagg + bias column)
    unsigned bgen[16][2];        // per-head B_gen fragments (W1b columns)

#define ISSUE_B(kt, buf)                                                              \
    do {                                                                              \
        _Pragma("unroll")                                                             \
        for (int c = 0; c < 2; c++) {                                                 \
            int ch = bc0 + c;                                                         \
            unsigned d_ = (unsigned)__cvta_generic_to_shared(                         \
                &Bs[buf][bswz(brow, ch * 8)]);                                        \
            const __half* s_ = &g_W2h[(size_t)((kt) * 32 + brow) * HID + ch * 8];     \
            asm volatile("cp.async.ca.shared.global [%0], [%1], 16;" ::               \
                         "r"(d_), "l"(s_));                                           \
        }                                                                             \
    } while (0)

    // xagg value with bias-1 column at k=9, zeros beyond
#define XV(row, k) ((k) < 9 ? g_xagg[(m0 + (row)) * 72 + h * 9 + (k)] \
                            : ((k) == 9 ? 1.f : 0.f))

    ISSUE_B(0, 0);
    asm volatile("cp.async.commit_group;");

    for (int h = 0; h < HEADS; h++) {
        // ---- per-head register staging (overlaps with cp.async in flight)
#pragma unroll
        for (int mt = 0; mt < 2; mt++) {
            int r0 = wm * 32 + mt * 16 + r4;
            agen[mt][0] = h2u(__floats2half2_rn(XV(r0,     kg),     XV(r0,     kg + 1)));
            agen[mt][1] = h2u(__floats2half2_rn(XV(r0 + 8, kg),     XV(r0 + 8, kg + 1)));
            agen[mt][2] = h2u(__floats2half2_rn(XV(r0,     kg + 8), XV(r0,     kg + 9)));
            agen[mt][3] = h2u(__floats2half2_rn(XV(r0 + 8, kg + 8), XV(r0 + 8, kg + 9)));
        }
        {
            const __half* wb = g_W1b + h * (10 * HID);
#pragma unroll
            for (int T = 0; T < 16; T++) {
                int c = T * 8 + r4;
                __half w0 = wb[kg * HID + c];              // kg<=6 < 10 always
                __half w1 = wb[(kg + 1) * HID + c];
                bgen[T][0] = h2u(__halves2half2(w0, w1));
                __half w2 = (kg + 8 < 10) ? wb[(kg + 8) * HID + c] : __float2half(0.f);
                __half w3 = (kg + 9 < 10) ? wb[(kg + 9) * HID + c] : __float2half(0.f);
                bgen[T][1] = h2u(__halves2half2(w2, w3));
            }
        }

#pragma unroll
        for (int lc = 0; lc < 4; lc++) {
            int ct = h * 4 + lc;
            int buf = ct & 1;
            asm volatile("cp.async.wait_group 0;");
            __syncthreads();
            if (ct + 1 < 32) {
                ISSUE_B(ct + 1, buf ^ 1);
                asm volatile("cp.async.commit_group;");
            }

            // ---- generate A fragments for this 32-K chunk via gen-mma
            unsigned afr[2][2][4];
#pragma unroll
            for (int mt = 0; mt < 2; mt++)
#pragma unroll
                for (int ti = 0; ti < 4; ti++) {
                    float cg0 = 0.f, cg1 = 0.f, cg2 = 0.f, cg3 = 0.f;
                    asm volatile(
                        "mma.sync.aligned.m16n8k16.row.col.f32.f16.f16.f32 "
                        "{%0,%1,%2,%3}, {%4,%5,%6,%7}, {%8,%9}, {%0,%1,%2,%3};"
                        : "+f"(cg0), "+f"(cg1), "+f"(cg2), "+f"(cg3)
                        : "r"(agen[mt][0]), "r"(agen[mt][1]),
                          "r"(agen[mt][2]), "r"(agen[mt][3]),
                          "r"(bgen[lc * 4 + ti][0]), "r"(bgen[lc * 4 + ti][1]));
                    __half2 lo = __floats2half2_rn(fmaxf(cg0, 0.f), fmaxf(cg1, 0.f));
                    __half2 hi = __floats2half2_rn(fmaxf(cg2, 0.f), fmaxf(cg3, 0.f));
                    afr[mt][ti >> 1][(ti & 1) * 2 + 0] = h2u(lo);
                    afr[mt][ti >> 1][(ti & 1) * 2 + 1] = h2u(hi);
                }

            // ---- main mma over Bs[buf]
#pragma unroll
            for (int kh = 0; kh < 2; kh++) {
                unsigned b[8][2];
#pragma unroll
                for (int nt = 0; nt < 8; nt++) {
                    int r = kh * 16 + (lane & 15);
                    int cc = wn * 64 + nt * 8;
                    unsigned addr = (unsigned)__cvta_generic_to_shared(&Bs[buf][bswz(r, cc)]);
                    asm volatile("ldmatrix.sync.aligned.m8n8.x2.trans.shared.b16 {%0,%1}, [%2];"
                                 : "=r"(b[nt][0]), "=r"(b[nt][1]) : "r"(addr));
                }
#pragma unroll
                for (int mt = 0; mt < 2; mt++)
#pragma unroll
                    for (int nt = 0; nt < 8; nt++) {
                        asm volatile(
                            "mma.sync.aligned.m16n8k16.row.col.f32.f16.f16.f32 "
                            "{%0,%1,%2,%3}, {%4,%5,%6,%7}, {%8,%9}, {%0,%1,%2,%3};"
                            : "+f"(acc[mt][nt][0]), "+f"(acc[mt][nt][1]),
                              "+f"(acc[mt][nt][2]), "+f"(acc[mt][nt][3])
                            : "r"(afr[mt][kh][0]), "r"(afr[mt][kh][1]),
                              "r"(afr[mt][kh][2]), "r"(afr[mt][kh][3]),
                              "r"(b[nt][0]), "r"(b[nt][1]));
                    }
            }
        }
    }
#undef ISSUE_B
#undef XV

#pragma unroll
    for (int mt = 0; mt < 2; mt++) {
        size_t rbase = m0 + wm * 32 + mt * 16 + (lane >> 2);
#pragma unroll
        for (int nt = 0; nt < 8; nt++) {
            int col = wn * 64 + nt * 8 + (lane & 3) * 2;
            *(__half2*)&g_h2[rbase * HID + col] =
                __floats2half2_rn(acc[mt][nt][0], acc[mt][nt][1]);
            *(__half2*)&g_h2[(rbase + 8) * HID + col] =
                __floats2half2_rn(acc[mt][nt][2], acc[mt][nt][3]);
        }
    }
}

// ---------------- GAT2 attention logits (batched) ----------------
__global__ void __launch_bounds__(256) k_al2(const float* __restrict__ as2,
                                             const float* __restrict__ ad2) {
    int w = threadIdx.x >> 5, lane = threadIdx.x & 31;
    int n = blockIdx.x * 8 + w;
    int t = blockIdx.y;
    if (n >= NN) return;
    uint2 v = *(const uint2*)&g_h2[((size_t)t * NN + n) * HID + lane * 4];
    float2 f0 = __half22float2(*(__half2*)&v.x);
    float2 f1 = __half22float2(*(__half2*)&v.y);
    float4 a = *(const float4*)&as2[lane * 4];
    float4 d = *(const float4*)&ad2[lane * 4];
    float ps = f0.x * a.x + f0.y * a.y + f1.x * a.z + f1.y * a.w;
    float pd = f0.x * d.x + f0.y * d.y + f1.x * d.z + f1.y * d.w;
#pragma unroll
    for (int off = 16; off; off >>= 1) {
        ps += __shfl_xor_sync(FULL, ps, off);
        pd += __shfl_xor_sync(FULL, pd, off);
    }
    if (lane == 0) {
        g_als2[(size_t)t * NN + n] = ps;
        g_ald2[(size_t)t * NN + n] = pd;
    }
}

// ---------------- GAT2 softmax + aggregation (batched) ----------------
__global__ void __launch_bounds__(256) k_agg2(const float* __restrict__ b2) {
    int w = threadIdx.x >> 5, lane = threadIdx.x & 31;
    int n = blockIdx.x * 8 + w;
    int t = blockIdx.y;
    if (n >= NN) return;
    const __half* h2 = g_h2 + (size_t)t * NN * HID;
    const float* als = g_als2 + (size_t)t * NN;
    int start = g_rowptr[n];
    int deg = g_rowptr[n + 1] - start + 1;
    float aldn = g_ald2[(size_t)t * NN + n];

    float sum = 0.f;
    for (int i = lane; i < deg; i += 32) {
        int s = (i < deg - 1) ? g_col[start + i] : n;
        float l = als[s] + aldn;
        l = (l > 0.f) ? l : 0.2f * l;
        sum += __expf(l);
    }
#pragma unroll
    for (int off = 16; off; off >>= 1) sum += __shfl_xor_sync(FULL, sum, off);
    float inv = 1.f / (sum + 1e-16f);

    float a0 = 0.f, a1 = 0.f, a2 = 0.f, a3 = 0.f;
    const int* colp = &g_col[start];
    for (int i = 0; i < deg; i++) {
        int s = (i < deg - 1) ? colp[i] : n;
        float l = als[s] + aldn;
        l = (l > 0.f) ? l : 0.2f * l;
        float al = __expf(l) * inv;
        uint2 v = *(const uint2*)&h2[(size_t)s * HID + lane * 4];
        float2 f0 = __half22float2(*(__half2*)&v.x);
        float2 f1 = __half22float2(*(__half2*)&v.y);
        a0 += al * f0.x; a1 += al * f0.y;
        a2 += al * f1.x; a3 += al * f1.y;
    }
    float4 b = *(const float4*)&b2[lane * 4];
    __half2 p0 = __floats2half2_rn(fmaxf(a0 + b.x, 0.f), fmaxf(a1 + b.y, 0.f));
    __half2 p1 = __floats2half2_rn(fmaxf(a2 + b.z, 0.f), fmaxf(a3 + b.w, 0.f));
    uint2 o;
    o.x = *(unsigned*)&p0; o.y = *(unsigned*)&p1;
    *(uint2*)&g_out2h[((size_t)t * NN + n) * HID + lane * 4] = o;
}

// ---------------- deterministic mean pool (batched) ----------------
__global__ void __launch_bounds__(128) k_pool_a() {
    int c = threadIdx.x, b = blockIdx.x, t = blockIdx.y;
    int n0 = b * PCH, n1 = min(n0 + PCH, NN);
    float s = 0.f;
    for (int n = n0; n < n1; n++)
        s += __half2float(g_out2h[((size_t)t * NN + n) * HID + c]);
    g_partial[((size_t)t * PBLK + b) * HID + c] = s;
}

__global__ void __launch_bounds__(128) k_pool_b() {
    int c = threadIdx.x, t = blockIdx.x;
    float s = 0.f;
    for (int b = 0; b < PBLK; b++) s += g_partial[((size_t)t * PBLK + b) * HID + c];
    g_emb[t * HID + c] = s * (1.0f / NN);
}

// ---------------- GRU + output head: 384 threads, fp32, weights in registers ----------------
__global__ void __launch_bounds__(384) k_gru3(
    const float* __restrict__ wih, const float* __restrict__ whh,
    const float* __restrict__ bih, const float* __restrict__ bhh,
    const float* __restrict__ wout, const float* __restrict__ bout,
    float* __restrict__ out) {
    __shared__ float semb[TT * HID];
    __shared__ float sgi[TT * 384];
    __shared__ float sgh[384];
    __shared__ float sh[HID + 4];
    __shared__ float red[4];
    int tid = threadIdx.x;

    for (int i = tid; i < TT * HID; i += 384) semb[i] = g_emb[i];

    float wreg[HID];
    {
        const float* ws = &wih[(size_t)tid * HID];
#pragma unroll 16
        for (int i = 0; i < HID; i++) wreg[i] = ws[i];
        float bi = bih[tid];
        __syncthreads();
        for (int t = 0; t < TT; t++) {
            const float* e = &semb[t * HID];
            float s = bi;
#pragma unroll 16
            for (int i = 0; i < HID; i++) s += wreg[i] * e[i];
            sgi[t * 384 + tid] = s;
        }
    }
    {
        const float* ws = &whh[(size_t)tid * HID];
#pragma unroll 16
        for (int i = 0; i < HID; i++) wreg[i] = ws[i];
    }
    float bh = bhh[tid];
    if (tid < HID) sh[tid] = 0.f;
    __syncthreads();

    for (int t = 0; t < TT; t++) {
        float s = bh;
#pragma unroll 16
        for (int i = 0; i < HID; i++) s += wreg[i] * sh[i];
        sgh[tid] = s;
        __syncthreads();

        if (tid < HID) {
            int j = tid;
            float grv = sgi[t * 384 + j]       + sgh[j];
            float gzv = sgi[t * 384 + 128 + j] + sgh[128 + j];
            float gnv = sgi[t * 384 + 256 + j];
            float ghn = sgh[256 + j];
            float rr = 1.f / (1.f + __expf(-grv));
            float zz = 1.f / (1.f + __expf(-gzv));
            float nn = tanhf(gnv + rr * ghn);
            float hn = (1.f - zz) * nn + zz * sh[j];
            sh[j] = hn;
            float v = hn * wout[j];
#pragma unroll
            for (int o = 16; o; o >>= 1) v += __shfl_down_sync(FULL, v, o);
            if ((tid & 31) == 0) red[tid >> 5] = v;
        }
        __syncthreads();
        if (tid == 0) out[t] = red[0] + red[1] + red[2] + red[3] + bout[0];
    }
}

// ---------------- launch ----------------
extern "C" void kernel_launch(void* const* d_in, const int* in_sizes, int n_in,
                              void* d_out, int out_size) {
    const float* x    = (const float*)d_in[0];
    const void*  ei   = d_in[1];
    const float* W1   = (const float*)d_in[2];
    const float* as1  = (const float*)d_in[3];
    const float* ad1  = (const float*)d_in[4];
    const float* b1   = (const float*)d_in[5];
    const float* W2   = (const float*)d_in[6];
    const float* as2  = (const float*)d_in[7];
    const float* ad2  = (const float*)d_in[8];
    const float* b2   = (const float*)d_in[9];
    const float* wih  = (const float*)d_in[10];
    const float* whh  = (const float*)d_in[11];
    const float* bih  = (const float*)d_in[12];
    const float* bhh  = (const float*)d_in[13];
    const float* wout = (const float*)d_in[14];
    const float* bout = (const float*)d_in[15];
    float* out = (float*)d_out;

    k_zc<<<(NN + 255) / 256, 256>>>();
    k_count<<<(EE + 255) / 256, 256>>>(ei);
    k_prep<<<(D1 * HID + 255) / 256, 256>>>(W2, W1, as1, ad1, b1);
    k_logits1<<<(TT * NN + 255) / 256, 256>>>(x);
    k_scan<<<1, 1024>>>();
    k_fill<<<(EE + 255) / 256, 256>>>(ei);
    k_agg1x<<<dim3((NN + 7) / 8, TT), 256>>>(x);
    k_gemmt<<<MM / 128, 256>>>();
    k_al2<<<dim3((NN + 7) / 8, TT), 256>>>(as2, ad2);
    k_agg2<<<dim3((NN + 7) / 8, TT), 256>>>(b2);
    k_pool_a<<<dim3(PBLK, TT), 128>>>();
    k_pool_b<<<TT, 128>>>();
    k_gru3<<<1, 384>>>(wih, whh, bih, bhh, wout, bout, out);
}